// round 10
// baseline (speedup 1.0000x reference)
#include <cuda_runtime.h>
#include <cuda_bf16.h>
#include <cstdint>

#define NN 50000
#define EE 600000
#define DEPTH 8
#define NTHREADS 512
#define NBLK 98            // ceil(NN / 512)
#define EDGE_CAP 8192      // smem-staged edge records per CTA (64KB)

// ---------------- scratch (alloc-free rule: __device__ globals) ----------------
__device__ __align__(16) float g_y[NN * 128];
__device__ __align__(16) __nv_bfloat16 g_wt_hi[262144];
__device__ __align__(16) __nv_bfloat16 g_wt_lo[262144];
// CSR per depth
__device__ int  g_cnt[DEPTH * NN];
__device__ int  g_cur[DEPTH * NN];
__device__ int  g_rp [DEPTH * (NN + 1)];
__device__ int  g_part[DEPTH * NBLK];
__device__ __align__(16) int2 g_cv[DEPTH * EE + 2];   // {dst, val bits}, +2 pad for 16B tail

// ---------------- helpers ----------------
__device__ __forceinline__ uint32_t smem_to_u32(const void* smem_ptr) {
    uint32_t addr;
    asm("{ .reg .u64 tmp; cvta.to.shared.u64 tmp, %1; cvt.u32.u64 %0, tmp; }"
        : "=r"(addr) : "l"(smem_ptr));
    return addr;
}

__device__ __forceinline__ void ldmx4(uint32_t* d, uint32_t addr) {
    asm volatile("ldmatrix.sync.aligned.m8n8.x4.shared.b16 {%0,%1,%2,%3}, [%4];"
                 : "=r"(d[0]), "=r"(d[1]), "=r"(d[2]), "=r"(d[3]) : "r"(addr));
}

__device__ __forceinline__ void mma16816(float* c, const uint32_t* a, const uint32_t* b) {
    asm volatile(
        "mma.sync.aligned.m16n8k16.row.col.f32.bf16.bf16.f32 "
        "{%0,%1,%2,%3},{%4,%5,%6,%7},{%8,%9},{%0,%1,%2,%3};"
        : "+f"(c[0]), "+f"(c[1]), "+f"(c[2]), "+f"(c[3])
        : "r"(a[0]), "r"(a[1]), "r"(a[2]), "r"(a[3]), "r"(b[0]), "r"(b[1]));
}

__device__ __forceinline__ void cp16(uint32_t smem_addr, const void* gptr, int srcbytes) {
    asm volatile("cp.async.cg.shared.global [%0], [%1], 16, %2;"
                 :: "r"(smem_addr), "l"(gptr), "r"(srcbytes) : "memory");
}
#define CP_COMMIT() asm volatile("cp.async.commit_group;" ::: "memory")
#define CP_WAIT(n)  asm volatile("cp.async.wait_group %0;" :: "n"(n) : "memory")

// swizzled byte offset within a 128x32 bf16 tile (row stride 64B, 16B groups XORed)
__device__ __forceinline__ uint32_t swz(int row, int c16) {
    return (uint32_t)(row * 64) + (uint32_t)(((c16 ^ ((row >> 1) & 3)) << 4));
}

__device__ __forceinline__ void split1(float v, __nv_bfloat16& h, __nv_bfloat16& l) {
    h = __float2bfloat16(v);
    l = __float2bfloat16(v - __bfloat162float(h));
}

// ---- one K=32 chunk of split-bf16 MMA for one warp tile (MI m16-tiles x 32 cols).
template<int MI>
__device__ __forceinline__ void chunk_mma(uint32_t Abase, uint32_t Bbase,
                                          int mo, int no, int lid,
                                          float acc[MI][4][4])
{
    const int lrow = lid & 15;
    const int lc = lid >> 4;
#pragma unroll
    for (int ks = 0; ks < 2; ++ks) {
        const int cA = (ks << 1) + lc;
        uint32_t bfh[4][2], bfl[4][2];
#pragma unroll
        for (int jj = 0; jj < 2; ++jj) {
            const int row = no + jj * 16 + lrow;
            const uint32_t so = swz(row, cA);
            uint32_t r4[4];
            ldmx4(r4, Bbase + so);
            bfh[jj * 2 + 0][0] = r4[0]; bfh[jj * 2 + 0][1] = r4[2];
            bfh[jj * 2 + 1][0] = r4[1]; bfh[jj * 2 + 1][1] = r4[3];
            ldmx4(r4, Bbase + 8192u + so);
            bfl[jj * 2 + 0][0] = r4[0]; bfl[jj * 2 + 0][1] = r4[2];
            bfl[jj * 2 + 1][0] = r4[1]; bfl[jj * 2 + 1][1] = r4[3];
        }
#pragma unroll
        for (int i = 0; i < MI; ++i) {
            const int row = mo + i * 16 + lrow;
            const uint32_t so = swz(row, cA);
            uint32_t afh[4], afl[4];
            ldmx4(afh, Abase + so);
            ldmx4(afl, Abase + 8192u + so);
#pragma unroll
            for (int j = 0; j < 4; ++j) {
                mma16816(acc[i][j], afh, bfh[j]);
                mma16816(acc[i][j], afh, bfl[j]);
                mma16816(acc[i][j], afl, bfh[j]);
            }
        }
    }
}

// ---- epilogue into act smem: bias + leaky-relu + bf16 split ----
template<int MI>
__device__ __forceinline__ void epi_to_act(float acc[MI][4][4], const float* bias,
                                           uint32_t act, int mo, int no_g, int lid)
{
    const int g = lid >> 2;
    const int t2c = (lid & 3) << 1;
#pragma unroll
    for (int i = 0; i < MI; ++i) {
        const int row0 = mo + i * 16 + g;
#pragma unroll
        for (int j = 0; j < 4; ++j) {
            const int col = no_g + j * 8 + t2c;
            const float2 bv = *(const float2*)(bias + col);
            const uint32_t cbase = act + (uint32_t)(col >> 5) * 16384u;
            const int c16 = (col & 31) >> 3;
            const uint32_t sub = (uint32_t)((col & 7) << 1);
#pragma unroll
            for (int h = 0; h < 2; ++h) {
                const int row = row0 + h * 8;
                float ox = acc[i][j][h * 2 + 0] + bv.x;
                float oy = acc[i][j][h * 2 + 1] + bv.y;
                ox = ox >= 0.f ? ox : 0.01f * ox;
                oy = oy >= 0.f ? oy : 0.01f * oy;
                __nv_bfloat16 hx, lx, hy, ly;
                split1(ox, hx, lx);
                split1(oy, hy, ly);
                uint32_t hp = (uint32_t)__bfloat16_as_ushort(hx) | ((uint32_t)__bfloat16_as_ushort(hy) << 16);
                uint32_t lp = (uint32_t)__bfloat16_as_ushort(lx) | ((uint32_t)__bfloat16_as_ushort(ly) << 16);
                const uint32_t ad = cbase + swz(row, c16) + sub;
                asm volatile("st.shared.b32 [%0], %1;" :: "r"(ad), "r"(hp) : "memory");
                asm volatile("st.shared.b32 [%0], %1;" :: "r"(ad + 8192u), "r"(lp) : "memory");
            }
        }
    }
}

// ---- write one gathered/split A row-quad into ACT ----
__device__ __forceinline__ void store_a_row(char* smem, int r, int lid, float4 a4)
{
    __nv_bfloat16 h0, l0, h1, l1, h2, l2, h3, l3;
    split1(a4.x, h0, l0); split1(a4.y, h1, l1);
    split1(a4.z, h2, l2); split1(a4.w, h3, l3);
    uint2 hp = make_uint2((uint32_t)__bfloat16_as_ushort(h0) | ((uint32_t)__bfloat16_as_ushort(h1) << 16),
                          (uint32_t)__bfloat16_as_ushort(h2) | ((uint32_t)__bfloat16_as_ushort(h3) << 16));
    uint2 lp = make_uint2((uint32_t)__bfloat16_as_ushort(l0) | ((uint32_t)__bfloat16_as_ushort(l1) << 16),
                          (uint32_t)__bfloat16_as_ushort(l2) | ((uint32_t)__bfloat16_as_ushort(l3) << 16));
    const int col = lid << 2;
    const uint32_t off = (uint32_t)(col >> 5) * 16384u
                       + swz(r, (col & 31) >> 3) + ((col & 4) ? 8u : 0u);
    *(uint2*)(smem + off) = hp;
    *(uint2*)(smem + off + 8192u) = lp;
}

// ---------------- fused MLP3 (fp32 in / fp32 out, optional residual+CSR gather) --
__global__ __launch_bounds__(NTHREADS, 1)
void fused_mlp3(const float* __restrict__ Ag,
                const __nv_bfloat16* __restrict__ W1h, const __nv_bfloat16* __restrict__ W1l,
                const __nv_bfloat16* __restrict__ W2h, const __nv_bfloat16* __restrict__ W2l,
                const __nv_bfloat16* __restrict__ W3h, const __nv_bfloat16* __restrict__ W3l,
                const float* __restrict__ b1, const float* __restrict__ b2,
                const float* __restrict__ b3,
                const int* __restrict__ rpg, const int2* __restrict__ cvg,
                const float* __restrict__ yg,
                float* __restrict__ Cf, const float* __restrict__ xin,
                const float* __restrict__ maskp, int Nrows)
{
    extern __shared__ char smem[];
    const uint32_t sb = smem_to_u32(smem);
    const uint32_t ACT = sb;                 // 128KB: chunk c at +c*16384 {hi, +8192 lo}
    const uint32_t STG = sb + 131072u;       // 96KB stage region
    const uint32_t EDG = sb + 65536u;        // ACT slots 4..7 (free during layer-1 A)

    const int tid = threadIdx.x;
    const int wid = tid >> 5;
    const int lid = tid & 31;
    const int bm = blockIdx.x * 128;
    const int mo = (wid >> 3) * 64;
    const int no_g = (wid & 7) * 32;
    const int nb = no_g >> 7;
    const int no_l = no_g & 127;
    const int mo3 = (wid >> 2) * 32;
    const int no3 = (wid & 3) * 32;

    auto issueB = [&](const __nv_bfloat16* Wh, const __nv_bfloat16* Wl,
                      int kstride, int c, int iters, int stgsz) {
        const int k0 = c << 5;
        const uint32_t st = STG + (uint32_t)(c % 3) * (uint32_t)stgsz;
        for (int it = 0; it < iters; ++it) {
            const int q = it * NTHREADS + tid;
            const int reg = q >> 9;
            const int w = q & 511;
            const int row = w >> 2;
            const int c16 = w & 3;
            const int blk = reg >> 1;
            const __nv_bfloat16* base = (reg & 1) ? Wl : Wh;
            const __nv_bfloat16* src = base + (size_t)(blk * 128 + row) * kstride + k0 + (c16 << 3);
            cp16(st + (uint32_t)reg * 8192u + swz(row, c16), src, 16);
        }
        CP_COMMIT();
    };

    float acc[4][4][4];

    // ================= layer 1: K=128 (4 chunks), 32KB stages =================
    // In gather mode, stage the CTA's contiguous CSR slice first (own cp group).
    int al = 0, stcnt = 0;
    bool fits = false;
    if (cvg) {
        const int ebeg0 = rpg[bm];
        const int eendB = rpg[(bm + 128 < Nrows) ? bm + 128 : Nrows];
        al = ebeg0 & ~1;                     // 16B-aligned record start
        stcnt = eendB - al;
        fits = (stcnt <= EDGE_CAP);
        if (fits && stcnt > 0) {
            for (int i = tid * 2; i < stcnt; i += NTHREADS * 2)
                cp16(EDG + (uint32_t)i * 8u, cvg + al + i, 16);
            CP_COMMIT();
        }
    }
    issueB(W1h, W1l, 128, 0, 4, 32768);
    issueB(W1h, W1l, 128, 1, 4, 32768);

    // ---- A into ACT slots 0..3 ----
    if (cvg) {
        const float4* yg4 = (const float4*)yg;
        if (fits) {
            if (stcnt > 0) { CP_WAIT(2); }   // edge group done (W0/W1 may pend)
            __syncthreads();
            const int2* esm = (const int2*)(smem + 65536);
#pragma unroll 1
            for (int q8 = 0; q8 < 8; ++q8) {
                const int r = (q8 << 4) + wid;          // interleave rows across warps
                const int nd = bm + r;
                float4 a0 = make_float4(0.f, 0.f, 0.f, 0.f);
                float4 a1 = make_float4(0.f, 0.f, 0.f, 0.f);
                if (nd < Nrows) {
                    int i = rpg[nd] - al;
                    const int end = rpg[nd + 1] - al;
#pragma unroll 1
                    for (; i + 2 <= end; i += 2) {
                        const int2 e0 = esm[i];
                        const int2 e1 = esm[i + 1];
                        const float v0 = __int_as_float(e0.y);
                        const float v1 = __int_as_float(e1.y);
                        const float4 y0 = yg4[(size_t)e0.x * 32 + lid];
                        const float4 y1 = yg4[(size_t)e1.x * 32 + lid];
                        a0.x += v0 * y0.x; a0.y += v0 * y0.y;
                        a0.z += v0 * y0.z; a0.w += v0 * y0.w;
                        a1.x += v1 * y1.x; a1.y += v1 * y1.y;
                        a1.z += v1 * y1.z; a1.w += v1 * y1.w;
                    }
                    if (i < end) {
                        const int2 e0 = esm[i];
                        const float v0 = __int_as_float(e0.y);
                        const float4 y0 = yg4[(size_t)e0.x * 32 + lid];
                        a0.x += v0 * y0.x; a0.y += v0 * y0.y;
                        a0.z += v0 * y0.z; a0.w += v0 * y0.w;
                    }
                }
                a0.x += a1.x; a0.y += a1.y; a0.z += a1.z; a0.w += a1.w;
                store_a_row(smem, r, lid, a0);
            }
        } else {
            // overflow fallback: direct global gather
#pragma unroll 1
            for (int q8 = 0; q8 < 8; ++q8) {
                const int r = (q8 << 4) + wid;
                const int nd = bm + r;
                float4 a4 = make_float4(0.f, 0.f, 0.f, 0.f);
                if (nd < Nrows) {
                    const int beg = rpg[nd], end = rpg[nd + 1];
                    for (int i = beg; i < end; ++i) {
                        const int2 e = cvg[i];
                        const float v = __int_as_float(e.y);
                        const float4 yv = yg4[(size_t)e.x * 32 + lid];
                        a4.x += v * yv.x; a4.y += v * yv.y;
                        a4.z += v * yv.z; a4.w += v * yv.w;
                    }
                }
                store_a_row(smem, r, lid, a4);
            }
        }
    } else {
        const int arow = tid >> 2;
        const int acol0 = (tid & 3) << 5;
        const int grow = bm + arow;
        const float* arp = Ag + (size_t)grow * 128 + acol0;
#pragma unroll
        for (int i = 0; i < 8; ++i) {
            const int col = acol0 + i * 4;
            float4 v = (grow < Nrows) ? *(const float4*)(arp + i * 4)
                                      : make_float4(0.f, 0.f, 0.f, 0.f);
            __nv_bfloat16 h0, l0, h1, l1, h2, l2, h3, l3;
            split1(v.x, h0, l0); split1(v.y, h1, l1);
            split1(v.z, h2, l2); split1(v.w, h3, l3);
            uint2 hp = make_uint2((uint32_t)__bfloat16_as_ushort(h0) | ((uint32_t)__bfloat16_as_ushort(h1) << 16),
                                  (uint32_t)__bfloat16_as_ushort(h2) | ((uint32_t)__bfloat16_as_ushort(h3) << 16));
            uint2 lp = make_uint2((uint32_t)__bfloat16_as_ushort(l0) | ((uint32_t)__bfloat16_as_ushort(l1) << 16),
                                  (uint32_t)__bfloat16_as_ushort(l2) | ((uint32_t)__bfloat16_as_ushort(l3) << 16));
            const uint32_t off = (uint32_t)(col >> 5) * 16384u
                               + swz(arow, (col & 31) >> 3) + ((col & 4) ? 8u : 0u);
            *(uint2*)(smem + off) = hp;
            *(uint2*)(smem + off + 8192u) = lp;
        }
    }

#pragma unroll
    for (int i = 0; i < 4; ++i)
#pragma unroll
        for (int j = 0; j < 4; ++j)
#pragma unroll
            for (int q = 0; q < 4; ++q) acc[i][j][q] = 0.f;

    for (int c = 0; c < 4; ++c) {
        if (c < 3) { CP_WAIT(1); } else { CP_WAIT(0); }
        __syncthreads();
        if (c + 2 < 4) issueB(W1h, W1l, 128, c + 2, 4, 32768);
        const uint32_t st = STG + (uint32_t)(c % 3) * 32768u;
        chunk_mma<4>(ACT + (uint32_t)c * 16384u, st + (uint32_t)nb * 16384u,
                     mo, no_l, lid, acc);
    }
    __syncthreads();
    issueB(W2h, W2l, 256, 0, 4, 32768);
    issueB(W2h, W2l, 256, 1, 4, 32768);
    epi_to_act<4>(acc, b1, ACT, mo, no_g, lid);

    // ================= layer 2: K=256 (8 chunks) =================
#pragma unroll
    for (int i = 0; i < 4; ++i)
#pragma unroll
        for (int j = 0; j < 4; ++j)
#pragma unroll
            for (int q = 0; q < 4; ++q) acc[i][j][q] = 0.f;

    for (int c = 0; c < 8; ++c) {
        if (c < 7) { CP_WAIT(1); } else { CP_WAIT(0); }
        __syncthreads();
        if (c + 2 < 8) issueB(W2h, W2l, 256, c + 2, 4, 32768);
        const uint32_t st = STG + (uint32_t)(c % 3) * 32768u;
        chunk_mma<4>(ACT + (uint32_t)c * 16384u, st + (uint32_t)nb * 16384u,
                     mo, no_l, lid, acc);
    }
    __syncthreads();
    issueB(W3h, W3l, 256, 0, 2, 16384);
    issueB(W3h, W3l, 256, 1, 2, 16384);
    epi_to_act<4>(acc, b2, ACT, mo, no_g, lid);

    // ================= layer 3: K=256 (8 chunks), M=128, 16KB stages =============
    float (&acc3)[2][4][4] = *reinterpret_cast<float(*)[2][4][4]>(acc);
#pragma unroll
    for (int i = 0; i < 2; ++i)
#pragma unroll
        for (int j = 0; j < 4; ++j)
#pragma unroll
            for (int q = 0; q < 4; ++q) acc3[i][j][q] = 0.f;

    for (int c = 0; c < 8; ++c) {
        if (c < 7) { CP_WAIT(1); } else { CP_WAIT(0); }
        __syncthreads();
        if (c + 2 < 8) issueB(W3h, W3l, 256, c + 2, 2, 16384);
        chunk_mma<2>(ACT + (uint32_t)c * 16384u, STG + (uint32_t)(c % 3) * 16384u,
                     mo3, no3, lid, acc3);
    }

    // ---- final epilogue: bias + leaky-relu (+ optional masked residual) ----
    {
        const int g = lid >> 2;
        const int t2c = (lid & 3) << 1;
#pragma unroll
        for (int i = 0; i < 2; ++i) {
            const int row0 = bm + mo3 + i * 16 + g;
#pragma unroll
            for (int j = 0; j < 4; ++j) {
                const int col = no3 + j * 8 + t2c;
                const float2 bv = *(const float2*)(b3 + col);
#pragma unroll
                for (int h = 0; h < 2; ++h) {
                    const int row = row0 + h * 8;
                    if (row >= Nrows) continue;
                    float2 o;
                    o.x = acc3[i][j][h * 2 + 0] + bv.x;
                    o.y = acc3[i][j][h * 2 + 1] + bv.y;
                    o.x = o.x >= 0.f ? o.x : 0.01f * o.x;
                    o.y = o.y >= 0.f ? o.y : 0.01f * o.y;
                    const size_t off = (size_t)row * 128 + col;
                    if (xin) {
                        const float m = maskp[row];
                        const float2 xv = *(const float2*)(xin + off);
                        o.x = xv.x + m * o.x;
                        o.y = xv.y + m * o.y;
                    }
                    *(float2*)(Cf + off) = o;
                }
            }
        }
    }
}

// ---------------- weight prep: all 6 matrices, one launch ----------------
__global__ void prep_all(const float* __restrict__ h1, const float* __restrict__ h2,
                         const float* __restrict__ h3, const float* __restrict__ f1,
                         const float* __restrict__ f2, const float* __restrict__ f3,
                         __nv_bfloat16* __restrict__ hi, __nv_bfloat16* __restrict__ lo)
{
    int idx = blockIdx.x * blockDim.x + threadIdx.x;
    if (idx >= 262144) return;
    const float* W; int K, M, off, li;
    if      (idx <  32768) { W = h1; K = 128; M = 256; off = 0;      li = idx; }
    else if (idx <  98304) { W = h2; K = 256; M = 256; off = 32768;  li = idx - 32768; }
    else if (idx < 131072) { W = h3; K = 256; M = 128; off = 98304;  li = idx - 98304; }
    else if (idx < 163840) { W = f1; K = 128; M = 256; off = 131072; li = idx - 131072; }
    else if (idx < 229376) { W = f2; K = 256; M = 256; off = 163840; li = idx - 163840; }
    else                   { W = f3; K = 256; M = 128; off = 229376; li = idx - 229376; }
    int k = li / M, m = li - k * M;
    float v = W[li];
    __nv_bfloat16 h, l;
    split1(v, h, l);
    hi[off + (size_t)m * K + k] = h;
    lo[off + (size_t)m * K + k] = l;
}

// ---------------- CSR build ----------------
__global__ void zero_int(int* __restrict__ p, int n)
{
    int i = blockIdx.x * blockDim.x + threadIdx.x;
    if (i < n) p[i] = 0;
}

__global__ void hist_kernel(const int* __restrict__ src, int* __restrict__ cnt)
{
    int idx = blockIdx.x * blockDim.x + threadIdx.x;
    if (idx >= DEPTH * EE / 4) return;
    int4 s4 = ((const int4*)src)[idx];
    int d = (idx << 2) / EE;
    int* c = cnt + d * NN;
    atomicAdd(&c[s4.x], 1);
    atomicAdd(&c[s4.y], 1);
    atomicAdd(&c[s4.z], 1);
    atomicAdd(&c[s4.w], 1);
}

// phase A: per-block sums
__global__ void part_kernel(const int* __restrict__ cnt, int* __restrict__ part)
{
    const int blk = blockIdx.x;
    const int d = blk / NBLK, b = blk - d * NBLK;
    const int t = threadIdx.x;
    const int idx = b * 512 + t;
    int c = (idx < NN) ? cnt[d * NN + idx] : 0;
#pragma unroll
    for (int o = 16; o > 0; o >>= 1) c += __shfl_down_sync(0xFFFFFFFFu, c, o);
    __shared__ int wsum[16];
    if ((t & 31) == 0) wsum[t >> 5] = c;
    __syncthreads();
    if (t < 16) {
        int v = wsum[t];
#pragma unroll
        for (int o = 8; o > 0; o >>= 1) v += __shfl_down_sync(0xFFFFu, v, o);
        if (t == 0) part[blk] = v;
    }
}

// phase B: exclusive scan of NBLK partials per depth
__global__ void scanp_kernel(int* __restrict__ part)
{
    __shared__ int sm[128];
    const int d = blockIdx.x, t = threadIdx.x;
    int v = (t < NBLK) ? part[d * NBLK + t] : 0;
    sm[t] = v;
    __syncthreads();
    for (int o = 1; o < 128; o <<= 1) {
        int u = (t >= o) ? sm[t - o] : 0;
        __syncthreads();
        sm[t] += u;
        __syncthreads();
    }
    if (t < NBLK) part[d * NBLK + t] = sm[t] - v;
}

// phase C: local scan + offset -> rp, cur
__global__ void scan2_kernel(const int* __restrict__ cnt, const int* __restrict__ part,
                             int* __restrict__ rp, int* __restrict__ cur)
{
    const int blk = blockIdx.x;
    const int d = blk / NBLK, b = blk - d * NBLK;
    const int t = threadIdx.x;
    const int idx = b * 512 + t;
    const int lane = t & 31, warp = t >> 5;
    int c = (idx < NN) ? cnt[d * NN + idx] : 0;
    int v = c;
#pragma unroll
    for (int o = 1; o < 32; o <<= 1) {
        int u = __shfl_up_sync(0xFFFFFFFFu, v, o);
        if (lane >= o) v += u;
    }
    __shared__ int wt[16];
    if (lane == 31) wt[warp] = v;
    __syncthreads();
    if (warp == 0 && lane < 16) {
        int w = wt[lane];
#pragma unroll
        for (int o = 1; o < 16; o <<= 1) {
            int u = __shfl_up_sync(0xFFFFu, w, o);
            if (lane >= o) w += u;
        }
        wt[lane] = w;
    }
    __syncthreads();
    const int excl = (v - c) + (warp ? wt[warp - 1] : 0) + part[blk];
    if (idx < NN) {
        rp[d * (NN + 1) + idx] = excl;
        cur[d * NN + idx] = excl;
    }
    if (b == 0 && t == 0) rp[d * (NN + 1) + NN] = EE;
}

__global__ void fill_kernel(const int* __restrict__ src, const int* __restrict__ dst,
                            const float* __restrict__ vals, int* __restrict__ cur,
                            int2* __restrict__ cv)
{
    int idx = blockIdx.x * blockDim.x + threadIdx.x;
    if (idx >= DEPTH * EE / 4) return;
    int4 s4 = ((const int4*)src)[idx];
    int4 t4 = ((const int4*)dst)[idx];
    float4 v4 = ((const float4*)vals)[idx];
    int d = (idx << 2) / EE;
    int* cu = cur + d * NN;
    int2* cvd = cv + (size_t)d * EE;
    int p;
    p = atomicAdd(&cu[s4.x], 1); cvd[p] = make_int2(t4.x, __float_as_int(v4.x));
    p = atomicAdd(&cu[s4.y], 1); cvd[p] = make_int2(t4.y, __float_as_int(v4.y));
    p = atomicAdd(&cu[s4.z], 1); cvd[p] = make_int2(t4.z, __float_as_int(v4.z));
    p = atomicAdd(&cu[s4.w], 1); cvd[p] = make_int2(t4.w, __float_as_int(v4.w));
}

// ---------------- host orchestration ----------------
static const int FUSED_SMEM = 131072 + 98304;   // act 128KB + stages 96KB = 224KB

extern "C" void kernel_launch(void* const* d_in, const int* in_sizes, int n_in,
                              void* d_out, int out_size)
{
    const float* node_inputs = (const float*)d_in[0];
    const int*   edge_src    = (const int*)  d_in[1];
    const int*   edge_dst    = (const int*)  d_in[2];
    const float* adj_vals    = (const float*)d_in[3];
    const float* masks       = (const float*)d_in[4];
    const float* W_h1 = (const float*)d_in[5];
    const float* b_h1 = (const float*)d_in[6];
    const float* W_h2 = (const float*)d_in[7];
    const float* b_h2 = (const float*)d_in[8];
    const float* W_h3 = (const float*)d_in[9];
    const float* b_h3 = (const float*)d_in[10];
    const float* W_f1 = (const float*)d_in[11];
    const float* b_f1 = (const float*)d_in[12];
    const float* W_f2 = (const float*)d_in[13];
    const float* b_f2 = (const float*)d_in[14];
    const float* W_f3 = (const float*)d_in[15];
    const float* b_f3 = (const float*)d_in[16];

    float* x = (float*)d_out;

    float* y;
    __nv_bfloat16 *whi, *wlo;
    int *cnt, *cur, *rp, *partp;
    int2* cvp;
    cudaGetSymbolAddress((void**)&y,     g_y);
    cudaGetSymbolAddress((void**)&whi,   g_wt_hi);
    cudaGetSymbolAddress((void**)&wlo,   g_wt_lo);
    cudaGetSymbolAddress((void**)&cnt,   g_cnt);
    cudaGetSymbolAddress((void**)&cur,   g_cur);
    cudaGetSymbolAddress((void**)&rp,    g_rp);
    cudaGetSymbolAddress((void**)&partp, g_part);
    cudaGetSymbolAddress((void**)&cvp,   g_cv);

    cudaFuncSetAttribute(fused_mlp3, cudaFuncAttributeMaxDynamicSharedMemorySize, FUSED_SMEM);

    const int OH1 = 0, OH2 = 32768, OH3 = 98304, OF1 = 131072, OF2 = 163840, OF3 = 229376;

    // weight prep + CSR build (once per call)
    prep_all<<<262144 / 256, 256>>>(W_h1, W_h2, W_h3, W_f1, W_f2, W_f3, whi, wlo);
    zero_int<<<(DEPTH * NN + 255) / 256, 256>>>(cnt, DEPTH * NN);
    hist_kernel<<<(DEPTH * EE / 4 + 255) / 256, 256>>>(edge_src, cnt);
    part_kernel<<<DEPTH * NBLK, 512>>>(cnt, partp);
    scanp_kernel<<<DEPTH, 128>>>(partp);
    scan2_kernel<<<DEPTH * NBLK, 512>>>(cnt, partp, rp, cur);
    fill_kernel<<<(DEPTH * EE / 4 + 255) / 256, 256>>>(edge_src, edge_dst, adj_vals,
                                                       cur, cvp);

    const int GRID = (NN + 127) / 128;   // 391

    // embedding MLP: x = mlp3(node_inputs; W_h*)
    fused_mlp3<<<GRID, NTHREADS, FUSED_SMEM>>>(node_inputs,
        whi + OH1, wlo + OH1, whi + OH2, wlo + OH2, whi + OH3, wlo + OH3,
        b_h1, b_h2, b_h3, nullptr, nullptr, nullptr, x, nullptr, nullptr, NN);

    for (int d = 0; d < DEPTH; d++) {
        // y = mlp3(x)
        fused_mlp3<<<GRID, NTHREADS, FUSED_SMEM>>>(x,
            whi + OF1, wlo + OF1, whi + OF2, wlo + OF2, whi + OF3, wlo + OF3,
            b_f1, b_f2, b_f3, nullptr, nullptr, nullptr, y, nullptr, nullptr, NN);

        // x = x + mask[d] * mlp3(segment_sum(val*y[dst], src))  — gather fused in
        fused_mlp3<<<GRID, NTHREADS, FUSED_SMEM>>>(nullptr,
            whi + OF1, wlo + OF1, whi + OF2, wlo + OF2, whi + OF3, wlo + OF3,
            b_f1, b_f2, b_f3, rp + d * (NN + 1), cvp + (size_t)d * EE, y,
            x, x, masks + (size_t)d * NN, NN);
    }
}